// round 14
// baseline (speedup 1.0000x reference)
#include <cuda_runtime.h>

// Structured mesh: NX=NY=1000 cells, nodes 1001x1001 float2.
#define NL        1001              // nodes per row
#define RT        5                 // cell rows per tile
#define CT        125               // cell cols per tile
#define GX        8                 // col tiles
#define GY        200               // row tiles
#define NBLK      (GX * GY)         // 1600
#define THREADS   128
#define W4        64                // float4 per smem row (128 float2)
#define NROWS     (RT + 1)          // 6 node rows per tile
#define TOTAL2    (NL * NL)         // 1002001 float2 elements (odd!)

__device__ double g_partials[NBLK];
__device__ unsigned int g_count = 0;

__device__ __forceinline__ void tri_geom(const float x[3], const float y[3],
                                         const float dNs[3][2],
                                         float dNp[3][2], float& det)
{
    float J00 = 0.f, J01 = 0.f, J10 = 0.f, J11 = 0.f;
    #pragma unroll
    for (int a = 0; a < 3; a++) {
        J00 += x[a] * dNs[a][0];
        J01 += x[a] * dNs[a][1];
        J10 += y[a] * dNs[a][0];
        J11 += y[a] * dNs[a][1];
    }
    det = J00 * J11 - J01 * J10;
    float inv = 1.0f / det;
    float i00 =  J11 * inv, i01 = -J01 * inv;
    float i10 = -J10 * inv, i11 =  J00 * inv;
    #pragma unroll
    for (int a = 0; a < 3; a++) {
        dNp[a][0] = dNs[a][0] * i00 + dNs[a][1] * i10;
        dNp[a][1] = dNs[a][0] * i01 + dNs[a][1] * i11;
    }
}

__device__ __forceinline__ float dot2(float2 a, float2 b) {
    return fmaf(a.x, b.x, a.y * b.y);
}

// Vertical-strip qc (cell nodes p: 0=(i,j) 1=(i,j+1) 2=(i+1,j) 3=(i+1,j+1)):
//  0:qd0 1:qd2 2:qd0+qd2 | 3:qd1 4:qd3 5:qd1+qd3 | 6:qo01 7:qo23 8:qo01+qo23
//  9:qo02(VA) 10:qo13(VB) 11:qo03(D1) 12:qo12(D2)
__global__ void __launch_bounds__(THREADS)
energy_kernel(const float* __restrict__ vals,     // (n_nodes, 2)
              const float* __restrict__ Nmat,     // (3, 3)
              const float* __restrict__ dNmat,    // (3, 3, 2)
              const float* __restrict__ qw,       // (3,)
              float* __restrict__ out)
{
    __shared__ float4 tile4[NROWS][W4];           // 6 x 64 x 16B = 6 KB

    const int bx = blockIdx.x;                    // 0..7 col tile
    const int by = blockIdx.y;                    // 0..199 row tile
    const int tid = threadIdx.x;
    const int i0 = by * RT;
    const int j0 = bx * CT;
    const bool corner_tile = (bx == GX - 1) && (by == GY - 1);

    // ---- cooperative coalesced staging, issued first ----
    // Row r: global node row g = i0 + r. Start float2 s = g*NL + j0 - pr with
    // pr = (g + j0) & 1 making s even (NL is odd). smem col of global col c is
    // (c - j0) + pr.
    const float4* __restrict__ v4 = (const float4*)vals;
    const float2* __restrict__ v2 = (const float2*)vals;
    #pragma unroll
    for (int idx = tid; idx < NROWS * W4; idx += THREADS) {
        int r = idx >> 6;                         // / W4
        int m = idx & (W4 - 1);
        int g = i0 + r;
        int pr = (g + j0) & 1;
        int s = g * NL + j0 - pr;                 // even
        if (corner_tile && r == RT && m == W4 - 1) {
            // float4 m=63 would read float2 index TOTAL2 (OOB by one).
            // Only the corner node (row 1000, col 1000 -> smem float2 126,
            // since pr=1 there) is needed; patch it scalar.
            ((float2*)&tile4[RT][0])[126] = __ldg(v2 + (TOTAL2 - 1));
        } else {
            tile4[r][m] = __ldg(v4 + (s >> 1) + m);
        }
    }

    // ---- per-thread coefficient derivation (overlaps load latency) ----
    float qc[13];
    {
        float Ns[3][3], dNs[3][2], w[3];
        #pragma unroll
        for (int q = 0; q < 3; q++) {
            #pragma unroll
            for (int a = 0; a < 3; a++) Ns[q][a] = __ldg(&Nmat[q * 3 + a]);
            w[q] = __ldg(&qw[q]);
        }
        #pragma unroll
        for (int a = 0; a < 3; a++) {
            dNs[a][0] = __ldg(&dNmat[a * 2 + 0]);
            dNs[a][1] = __ldg(&dNmat[a * 2 + 1]);
        }
        float W = w[0] + w[1] + w[2];

        float M[3][3];
        #pragma unroll
        for (int a = 0; a < 3; a++)
            #pragma unroll
            for (int b = 0; b < 3; b++) {
                float s = 0.f;
                #pragma unroll
                for (int q = 0; q < 3; q++) s += w[q] * Ns[q][a] * Ns[q][b];
                M[a][b] = s;
            }

        const float hx = (float)(1.0 / (NL - 1));
        const float hy = (float)(1.0 / (NL - 1));
        float dNp1[3][2], dNp2[3][2], det1, det2;
        float x1c[3] = {0.f, hx, hx}, y1c[3] = {0.f, 0.f, hy};
        tri_geom(x1c, y1c, dNs, dNp1, det1);
        float x2c[3] = {0.f, hx, 0.f}, y2c[3] = {0.f, hy, hy};
        tri_geom(x2c, y2c, dNs, dNp2, det2);

        float Q[4][4] = {};
        const int m1[3] = {0, 2, 3};   // tri1 = (n00, n10, n11)
        const int m2[3] = {0, 3, 1};   // tri2 = (n00, n11, n01)
        #pragma unroll
        for (int a = 0; a < 3; a++)
            #pragma unroll
            for (int b = 0; b < 3; b++) {
                float G1 = dNp1[a][0]*dNp1[b][0] + dNp1[a][1]*dNp1[b][1];
                float G2 = dNp2[a][0]*dNp2[b][0] + dNp2[a][1]*dNp2[b][1];
                Q[m1[a]][m1[b]] += 0.5f * det1 * (W * G1 + M[a][b]);
                Q[m2[a]][m2[b]] += 0.5f * det2 * (W * G2 + M[a][b]);
            }
        float qd0 = Q[0][0], qd1 = Q[1][1], qd2 = Q[2][2], qd3 = Q[3][3];
        float qo01 = Q[0][1] + Q[1][0];
        float qo02 = Q[0][2] + Q[2][0];
        float qo03 = Q[0][3] + Q[3][0];
        float qo12 = Q[1][2] + Q[2][1];
        float qo13 = Q[1][3] + Q[3][1];
        float qo23 = Q[2][3] + Q[3][2];
        qc[0] = qd0;  qc[1] = qd2;  qc[2] = qd0 + qd2;
        qc[3] = qd1;  qc[4] = qd3;  qc[5] = qd1 + qd3;
        qc[6] = qo01; qc[7] = qo23; qc[8] = qo01 + qo23;
        qc[9] = qo02; qc[10] = qo13; qc[11] = qo03; qc[12] = qo12;
    }

    __syncthreads();

    // ---- compute: thread j owns vertical strip of RT cells at column j0+j ----
    float local = 0.0f;
    if (tid < CT) {
        int j = tid;
        int pr0 = (i0 + j0) & 1;
        const float2* row0 = (const float2*)&tile4[0][0];
        float2 A0 = row0[j + pr0];
        float2 B0 = row0[j + 1 + pr0];

        float VA = 0.f, VB = 0.f, D1 = 0.f, D2 = 0.f;
        float aaI = 0.f, bbI = 0.f, abI = 0.f;
        float2 Ap = A0, Bp = B0;
        #pragma unroll
        for (int r = 1; r <= RT; r++) {
            int pr = (i0 + r + j0) & 1;
            const float2* rowr = (const float2*)&tile4[r][0];
            float2 Ac = rowr[j + pr];
            float2 Bc = rowr[j + 1 + pr];
            VA += dot2(Ap, Ac);
            VB += dot2(Bp, Bc);
            D1 += dot2(Ap, Bc);
            D2 += dot2(Bp, Ac);
            if (r < RT) {
                aaI += dot2(Ac, Ac);
                bbI += dot2(Bc, Bc);
                abI += dot2(Ac, Bc);
            }
            Ap = Ac; Bp = Bc;
        }

        local =
              qc[0] * dot2(A0, A0) + qc[1] * dot2(Ap, Ap) + qc[2] * aaI
            + qc[3] * dot2(B0, B0) + qc[4] * dot2(Bp, Bp) + qc[5] * bbI
            + qc[6] * dot2(A0, B0) + qc[7] * dot2(Ap, Bp) + qc[8] * abI
            + qc[9] * VA + qc[10] * VB + qc[11] * D1 + qc[12] * D2;
    }

    // ---- block reduction + fused finalize ----
    #pragma unroll
    for (int off = 16; off > 0; off >>= 1)
        local += __shfl_down_sync(0xFFFFFFFFu, local, off);

    __shared__ float warp_sums[THREADS / 32];
    __shared__ bool  is_last;
    int lane = tid & 31;
    int wid  = tid >> 5;
    if (lane == 0) warp_sums[wid] = local;
    __syncthreads();
    if (tid == 0) {
        float s = 0.f;
        #pragma unroll
        for (int ww = 0; ww < THREADS / 32; ww++) s += warp_sums[ww];
        g_partials[blockIdx.y * GX + blockIdx.x] = (double)s;
        __threadfence();
        unsigned int v = atomicAdd(&g_count, 1u);
        is_last = (v == (unsigned int)(NBLK - 1));
    }
    __syncthreads();

    if (is_last) {
        double s = 0.0;
        for (int idx = tid; idx < NBLK; idx += THREADS)
            s += g_partials[idx];
        #pragma unroll
        for (int off = 16; off > 0; off >>= 1)
            s += __shfl_down_sync(0xFFFFFFFFu, s, off);
        __shared__ double dsums[THREADS / 32];
        if (lane == 0) dsums[wid] = s;
        __syncthreads();
        if (tid == 0) {
            double tot = 0.0;
            #pragma unroll
            for (int ww = 0; ww < THREADS / 32; ww++) tot += dsums[ww];
            out[0] = (float)tot;
            g_count = 0;   // reset for next graph replay
        }
    }
}

extern "C" void kernel_launch(void* const* d_in, const int* in_sizes, int n_in,
                              void* d_out, int out_size) {
    const float* nodal_values = (const float*)d_in[0];
    const float* Nmat         = (const float*)d_in[3];
    const float* dNmat        = (const float*)d_in[4];
    const float* qw           = (const float*)d_in[5];
    float* out = (float*)d_out;

    dim3 grid(GX, GY);
    energy_kernel<<<grid, THREADS>>>(nodal_values, Nmat, dNmat, qw, out);
}

// round 15
// speedup vs baseline: 1.1662x; 1.1662x over previous
#include <cuda_runtime.h>

// Structured mesh: NX=NY=1000 cells, nodes 1001x1001 float2.
#define NL        1001              // nodes per row
#define RT        10                // cell rows per tile
#define CT        250               // cell cols per tile
#define GX        4                 // col tiles
#define GY        100               // row tiles
#define NBLK      (GX * GY)         // 400
#define THREADS   256
#define W4        127               // float4 of real data per smem row
#define W4P       128               // padded smem row width (float4)
#define NROWS     (RT + 1)          // 11 node rows per tile
#define TOTAL2    (NL * NL)         // 1002001 float2 elements

__device__ double g_partials[NBLK];
__device__ unsigned int g_count = 0;

__device__ __forceinline__ void tri_geom(const float x[3], const float y[3],
                                         const float dNs[3][2],
                                         float dNp[3][2], float& det)
{
    float J00 = 0.f, J01 = 0.f, J10 = 0.f, J11 = 0.f;
    #pragma unroll
    for (int a = 0; a < 3; a++) {
        J00 += x[a] * dNs[a][0];
        J01 += x[a] * dNs[a][1];
        J10 += y[a] * dNs[a][0];
        J11 += y[a] * dNs[a][1];
    }
    det = J00 * J11 - J01 * J10;
    float inv = 1.0f / det;
    float i00 =  J11 * inv, i01 = -J01 * inv;
    float i10 = -J10 * inv, i11 =  J00 * inv;
    #pragma unroll
    for (int a = 0; a < 3; a++) {
        dNp[a][0] = dNs[a][0] * i00 + dNs[a][1] * i10;
        dNp[a][1] = dNs[a][0] * i01 + dNs[a][1] * i11;
    }
}

__device__ __forceinline__ float dot2(float2 a, float2 b) {
    return fmaf(a.x, b.x, a.y * b.y);
}

// Vertical-strip qc (cell nodes p: 0=(i,j) 1=(i,j+1) 2=(i+1,j) 3=(i+1,j+1)):
//  0:qd0 1:qd2 2:qd0+qd2 | 3:qd1 4:qd3 5:qd1+qd3 | 6:qo01 7:qo23 8:qo01+qo23
//  9:qo02(VA) 10:qo13(VB) 11:qo03(D1) 12:qo12(D2)
__global__ void __launch_bounds__(THREADS)
energy_kernel(const float* __restrict__ vals,     // (n_nodes, 2)
              const float* __restrict__ Nmat,     // (3, 3)
              const float* __restrict__ dNmat,    // (3, 3, 2)
              const float* __restrict__ qw,       // (3,)
              float* __restrict__ out)
{
    __shared__ float4 tile4[NROWS][W4P];          // 11 x 128 x 16B = 22.5 KB
    __shared__ float  qcs[13];

    const int bx = blockIdx.x;                    // 0..3 col tile
    const int by = blockIdx.y;                    // 0..99 row tile
    const int tid = threadIdx.x;
    const int i0 = by * RT;                       // even
    const int j0 = bx * CT;                       // even
    const int shift = (bx == GX - 1) ? 2 : 0;     // keep right edge in window
    const bool corner_tile = (bx == GX - 1) && (by == GY - 1);

    const float4* __restrict__ v4 = (const float4*)vals;
    const float2* __restrict__ v2 = (const float2*)vals;

    if (tid >= 128) {
        // ---- staging threads: warps 4-7, one smem column each ----
        int m = tid - 128;
        if (m < W4) {
            bool corner_patch = corner_tile && (m == W4 - 1);
            float4 tmp[NROWS];
            #pragma unroll
            for (int r = 0; r < NROWS; r++) {
                int pr = r & 1;                   // i0,j0 even -> parity of row
                int s = (i0 + r) * NL + j0 - shift - pr;   // even float2 start
                // For the corner tile's last float4 of the last row, clamp the
                // address (real value patched below) to avoid the 8B overread.
                int mm = (corner_patch && r == RT) ? (m - 1) : m;
                tmp[r] = __ldg(v4 + (s >> 1) + mm);
            }
            #pragma unroll
            for (int r = 0; r < NROWS; r++)
                tile4[r][m] = tmp[r];
            if (corner_patch) {
                // mesh corner node (row 1000, col 1000) -> smem f2 col 252
                ((float2*)&tile4[RT][0])[252] = __ldg(v2 + (TOTAL2 - 1));
            }
        }
    } else if (tid == 0) {
        // ---- single-thread coefficient derivation (hides under staging) ----
        float Ns[3][3], dNs[3][2], w[3];
        #pragma unroll
        for (int q = 0; q < 3; q++) {
            #pragma unroll
            for (int a = 0; a < 3; a++) Ns[q][a] = __ldg(&Nmat[q * 3 + a]);
            w[q] = __ldg(&qw[q]);
        }
        #pragma unroll
        for (int a = 0; a < 3; a++) {
            dNs[a][0] = __ldg(&dNmat[a * 2 + 0]);
            dNs[a][1] = __ldg(&dNmat[a * 2 + 1]);
        }
        float W = w[0] + w[1] + w[2];

        float M[3][3];
        #pragma unroll
        for (int a = 0; a < 3; a++)
            #pragma unroll
            for (int b = 0; b < 3; b++) {
                float s = 0.f;
                #pragma unroll
                for (int q = 0; q < 3; q++) s += w[q] * Ns[q][a] * Ns[q][b];
                M[a][b] = s;
            }

        const float hx = (float)(1.0 / (NL - 1));
        const float hy = (float)(1.0 / (NL - 1));
        float dNp1[3][2], dNp2[3][2], det1, det2;
        float x1c[3] = {0.f, hx, hx}, y1c[3] = {0.f, 0.f, hy};
        tri_geom(x1c, y1c, dNs, dNp1, det1);
        float x2c[3] = {0.f, hx, 0.f}, y2c[3] = {0.f, hy, hy};
        tri_geom(x2c, y2c, dNs, dNp2, det2);

        float Q[4][4] = {};
        const int m1[3] = {0, 2, 3};   // tri1 = (n00, n10, n11)
        const int m2[3] = {0, 3, 1};   // tri2 = (n00, n11, n01)
        #pragma unroll
        for (int a = 0; a < 3; a++)
            #pragma unroll
            for (int b = 0; b < 3; b++) {
                float G1 = dNp1[a][0]*dNp1[b][0] + dNp1[a][1]*dNp1[b][1];
                float G2 = dNp2[a][0]*dNp2[b][0] + dNp2[a][1]*dNp2[b][1];
                Q[m1[a]][m1[b]] += 0.5f * det1 * (W * G1 + M[a][b]);
                Q[m2[a]][m2[b]] += 0.5f * det2 * (W * G2 + M[a][b]);
            }
        float qd0 = Q[0][0], qd1 = Q[1][1], qd2 = Q[2][2], qd3 = Q[3][3];
        float qo01 = Q[0][1] + Q[1][0];
        float qo02 = Q[0][2] + Q[2][0];
        float qo03 = Q[0][3] + Q[3][0];
        float qo12 = Q[1][2] + Q[2][1];
        float qo13 = Q[1][3] + Q[3][1];
        float qo23 = Q[2][3] + Q[3][2];
        qcs[0] = qd0;  qcs[1] = qd2;  qcs[2] = qd0 + qd2;
        qcs[3] = qd1;  qcs[4] = qd3;  qcs[5] = qd1 + qd3;
        qcs[6] = qo01; qcs[7] = qo23; qcs[8] = qo01 + qo23;
        qcs[9] = qo02; qcs[10] = qo13; qcs[11] = qo03; qcs[12] = qo12;
    }

    __syncthreads();

    // ---- compute: thread j owns vertical strip of RT cells at column j0+j ----
    float local = 0.0f;
    if (tid < CT) {
        int j = tid;
        const float2* row0 = (const float2*)&tile4[0][0];
        float2 A0 = row0[j + shift];              // r=0 has pr=0
        float2 B0 = row0[j + 1 + shift];

        float VA = 0.f, VB = 0.f, D1 = 0.f, D2 = 0.f;
        float aaI = 0.f, bbI = 0.f, abI = 0.f;
        float2 Ap = A0, Bp = B0;
        #pragma unroll
        for (int r = 1; r <= RT; r++) {
            int pr = r & 1;
            const float2* rowr = (const float2*)&tile4[r][0];
            float2 Ac = rowr[j + shift + pr];
            float2 Bc = rowr[j + 1 + shift + pr];
            VA += dot2(Ap, Ac);
            VB += dot2(Bp, Bc);
            D1 += dot2(Ap, Bc);
            D2 += dot2(Bp, Ac);
            if (r < RT) {
                aaI += dot2(Ac, Ac);
                bbI += dot2(Bc, Bc);
                abI += dot2(Ac, Bc);
            }
            Ap = Ac; Bp = Bc;
        }

        local =
              qcs[0] * dot2(A0, A0) + qcs[1] * dot2(Ap, Ap) + qcs[2] * aaI
            + qcs[3] * dot2(B0, B0) + qcs[4] * dot2(Bp, Bp) + qcs[5] * bbI
            + qcs[6] * dot2(A0, B0) + qcs[7] * dot2(Ap, Bp) + qcs[8] * abI
            + qcs[9] * VA + qcs[10] * VB + qcs[11] * D1 + qcs[12] * D2;
    }

    // ---- block reduction + fused finalize ----
    #pragma unroll
    for (int off = 16; off > 0; off >>= 1)
        local += __shfl_down_sync(0xFFFFFFFFu, local, off);

    __shared__ float warp_sums[THREADS / 32];
    __shared__ bool  is_last;
    int lane = tid & 31;
    int wid  = tid >> 5;
    if (lane == 0) warp_sums[wid] = local;
    __syncthreads();
    if (tid == 0) {
        float s = 0.f;
        #pragma unroll
        for (int ww = 0; ww < THREADS / 32; ww++) s += warp_sums[ww];
        g_partials[blockIdx.y * GX + blockIdx.x] = (double)s;
        __threadfence();
        unsigned int v = atomicAdd(&g_count, 1u);
        is_last = (v == (unsigned int)(NBLK - 1));
    }
    __syncthreads();

    if (is_last) {
        double s = 0.0;
        for (int idx = tid; idx < NBLK; idx += THREADS)
            s += g_partials[idx];
        #pragma unroll
        for (int off = 16; off > 0; off >>= 1)
            s += __shfl_down_sync(0xFFFFFFFFu, s, off);
        __shared__ double dsums[THREADS / 32];
        if (lane == 0) dsums[wid] = s;
        __syncthreads();
        if (tid == 0) {
            double tot = 0.0;
            #pragma unroll
            for (int ww = 0; ww < THREADS / 32; ww++) tot += dsums[ww];
            out[0] = (float)tot;
            g_count = 0;   // reset for next graph replay
        }
    }
}

extern "C" void kernel_launch(void* const* d_in, const int* in_sizes, int n_in,
                              void* d_out, int out_size) {
    const float* nodal_values = (const float*)d_in[0];
    const float* Nmat         = (const float*)d_in[3];
    const float* dNmat        = (const float*)d_in[4];
    const float* qw           = (const float*)d_in[5];
    float* out = (float*)d_out;

    dim3 grid(GX, GY);
    energy_kernel<<<grid, THREADS>>>(nodal_values, Nmat, dNmat, qw, out);
}